// round 14
// baseline (speedup 1.0000x reference)
#include <cuda_runtime.h>
#include <cstdint>

#define NN 10000     // nodes
#define KD 8         // out-degree
#define EE 80000     // edges
#define HDIM 512     // H*D

// Scratch (allocation-free rule: __device__ globals)
__device__ float g_nq[NN * HDIM];
__device__ float g_nk[NN * HDIM];
__device__ float g_nv[NN * HDIM];
__device__ float g_node[NN * HDIM];

// ---- packed f32x2 helpers ----
__device__ __forceinline__ unsigned long long pack2(float lo, float hi) {
    unsigned long long r;
    asm("mov.b64 %0, {%1, %2};" : "=l"(r) : "f"(lo), "f"(hi));
    return r;
}
__device__ __forceinline__ void ffma2(unsigned long long& d,
                                      unsigned long long a,
                                      unsigned long long b) {
    asm("fma.rn.f32x2 %0, %1, %2, %0;" : "+l"(d) : "l"(a), "l"(b));
}
__device__ __forceinline__ float2 unpack2(unsigned long long v) {
    float2 f;
    asm("mov.b64 {%0, %1}, %2;" : "=f"(f.x), "=f"(f.y) : "l"(v));
    return f;
}
__device__ __forceinline__ float f4c(const float4& v, int i) {
    return (i == 0) ? v.x : (i == 1) ? v.y : (i == 2) ? v.z : v.w;
}
__device__ __forceinline__ uint32_t to_tf32(float f) {
    uint32_t r;
    asm("cvt.rna.tf32.f32 %0, %1;" : "=r"(r) : "f"(f));
    return r;
}
__device__ __forceinline__ void mma_tf32(float4& d,
                                         uint32_t a0, uint32_t a1, uint32_t a2, uint32_t a3,
                                         uint32_t b0, uint32_t b1) {
    asm("mma.sync.aligned.m16n8k8.row.col.f32.tf32.tf32.f32 "
        "{%0,%1,%2,%3}, {%4,%5,%6,%7}, {%8,%9}, {%0,%1,%2,%3};"
        : "+f"(d.x), "+f"(d.y), "+f"(d.z), "+f"(d.w)
        : "r"(a0), "r"(a1), "r"(a2), "r"(a3), "r"(b0), "r"(b1));
}

// ---------------------------------------------------------------------------
// Kernel 1: fused QKV projection on the TENSOR pipe (tf32 mma.sync).
// Block: 128 threads (4 warps), tile 64 rows x 128 cols, K=64.
// Warp w owns rows [w*16, w*16+16); 16 n-tiles of 8 cols; 8 k-steps of 8.
// ---------------------------------------------------------------------------
__global__ __launch_bounds__(128) void proj_qkv_kernel(
    const float* __restrict__ X,
    const float* __restrict__ Wq, const float* __restrict__ bq,
    const float* __restrict__ Wk, const float* __restrict__ bk,
    const float* __restrict__ Wv, const float* __restrict__ bv)
{
    __shared__ uint32_t As[64][68];    // [row][k]   tf32 bits
    __shared__ uint32_t Bs[64][136];   // [k][col]   tf32 bits (8k+g banks distinct)

    int bx  = blockIdx.x;
    int sel = bx >> 2;
    int c0  = (bx & 3) * 128;
    int r0  = blockIdx.y * 64;
    int t   = threadIdx.x;

    const float* W    = (sel == 0) ? Wq : (sel == 1) ? Wk : Wv;
    const float* bias = (sel == 0) ? bq : (sel == 1) ? bk : bv;
    float*       outp = (sel == 0) ? g_nq : (sel == 1) ? g_nk : g_nv;

    // stage X tile (64 rows x 64 k) as tf32
    #pragma unroll
    for (int i = 0; i < 8; i++) {
        int idx = t + i * 128;
        int row = idx >> 4, k4 = idx & 15;
        float4 v = make_float4(0.f, 0.f, 0.f, 0.f);
        if (r0 + row < NN) v = *(const float4*)&X[(r0 + row) * 64 + k4 * 4];
        As[row][k4*4+0] = to_tf32(v.x); As[row][k4*4+1] = to_tf32(v.y);
        As[row][k4*4+2] = to_tf32(v.z); As[row][k4*4+3] = to_tf32(v.w);
    }
    // stage W tile (128 cols x 64 k) transposed to [k][col] as tf32
    #pragma unroll
    for (int i = 0; i < 16; i++) {
        int idx = t + i * 128;
        int c = idx >> 4, k4 = idx & 15;
        float4 w = *(const float4*)&W[(c0 + c) * 64 + k4 * 4];
        Bs[k4*4+0][c] = to_tf32(w.x); Bs[k4*4+1][c] = to_tf32(w.y);
        Bs[k4*4+2][c] = to_tf32(w.z); Bs[k4*4+3][c] = to_tf32(w.w);
    }
    __syncthreads();

    int warp = t >> 5, lane = t & 31;
    int g  = lane >> 2;      // groupID (0..7)
    int tg = lane & 3;       // thread-in-group (0..3)
    int mrow = warp * 16;

    float4 acc[16];
    #pragma unroll
    for (int i = 0; i < 16; i++) acc[i] = make_float4(0.f, 0.f, 0.f, 0.f);

    #pragma unroll
    for (int ks = 0; ks < 8; ks++) {
        int k0 = ks * 8;
        uint32_t a0 = As[mrow + g][k0 + tg];
        uint32_t a1 = As[mrow + g + 8][k0 + tg];
        uint32_t a2 = As[mrow + g][k0 + tg + 4];
        uint32_t a3 = As[mrow + g + 8][k0 + tg + 4];
        #pragma unroll
        for (int nt = 0; nt < 16; nt++) {
            int n0 = nt * 8;
            uint32_t b0 = Bs[k0 + tg][n0 + g];
            uint32_t b1 = Bs[k0 + tg + 4][n0 + g];
            mma_tf32(acc[nt], a0, a1, a2, a3, b0, b1);
        }
    }

    // epilogue: thread owns (rows mrow+g, mrow+g+8) x (cols 2*tg, 2*tg+1) per n-tile
    int row1 = r0 + mrow + g;
    int row2 = row1 + 8;
    bool ok1 = row1 < NN, ok2 = row2 < NN;
    #pragma unroll
    for (int nt = 0; nt < 16; nt++) {
        int n = c0 + nt * 8 + 2 * tg;
        float2 b2 = *(const float2*)&bias[n];
        if (ok1) *(float2*)&outp[(long)row1 * HDIM + n] =
            make_float2(acc[nt].x + b2.x, acc[nt].y + b2.y);
        if (ok2) *(float2*)&outp[(long)row2 * HDIM + n] =
            make_float2(acc[nt].z + b2.x, acc[nt].w + b2.y);
    }
}

// ---------------------------------------------------------------------------
// Kernel 2: warp-per-node fused pipeline (exact R11 version — best known).
// ---------------------------------------------------------------------------
__global__ __launch_bounds__(128) void node_edge_kernel(
    const float* __restrict__ edge_features,
    const int*   __restrict__ edge_index,
    const float* __restrict__ Weq, const float* __restrict__ beq,
    const float* __restrict__ Wev, const float* __restrict__ bev,
    const float* __restrict__ Wek, const float* __restrict__ bek,
    const float* __restrict__ Wel, const float* __restrict__ bel,
    const float* __restrict__ Wele, const float* __restrict__ bele,
    float* __restrict__ out_edge)
{
    __shared__ __align__(16) float s_Wel[8][68];  // [h][c]
    __shared__ float s_Wele[16][9];               // [de][h]
    __shared__ __align__(16) float s_ef[4][8][16];
    __shared__ __align__(16) float s_eq[4][8][68];   // eq, reused as eout
    __shared__ __align__(16) float s_ev[4][8][68];
    __shared__ __align__(16) float s_ek[4][8][68];
    __shared__ __align__(16) float s_att[4][8][4][8];
    __shared__ float s_sqk[4][8][8];
    __shared__ float s_ee[4][8][8];
    __shared__ float s_attn[4][8][8];

    int t    = threadIdx.x;
    int nd   = t >> 5;
    int lane = t & 31;
    int n    = blockIdx.x * 4 + nd;

    for (int i = t; i < 512; i += 128) s_Wel[i >> 6][i & 63] = Wel[i];
    s_Wele[t >> 3][t & 7] = Wele[t];
    __syncthreads();

    int ej = (lane < 8) ? edge_index[EE + n * 8 + lane] : 0;
    int e1r[8];
    #pragma unroll
    for (int j = 0; j < 8; j++) e1r[j] = __shfl_sync(0xffffffffu, ej, j);

    ((float4*)&s_ef[nd][0][0])[lane] =
        ((const float4*)(edge_features + (long)n * 128))[lane];

    // ---- phase 1: sqk head-aligned ----
    {
        int hh = lane >> 2, mm = lane & 3;
        const float4* qp = (const float4*)(g_nq + (long)n * 512);
        float4 q4[4];
        #pragma unroll
        for (int i = 0; i < 4; i++) q4[i] = qp[hh * 16 + mm + 4 * i];
        #pragma unroll
        for (int j = 0; j < 8; j++) {
            const float4* kp = (const float4*)(g_nk + (long)e1r[j] * 512);
            float s = 0.f;
            #pragma unroll
            for (int i = 0; i < 4; i++) {
                float4 kv = __ldg(&kp[hh * 16 + mm + 4 * i]);
                s += q4[i].x * kv.x + q4[i].y * kv.y + q4[i].z * kv.z + q4[i].w * kv.w;
            }
            s += __shfl_xor_sync(0xffffffffu, s, 1);
            s += __shfl_xor_sync(0xffffffffu, s, 2);
            if (mm == 0) s_sqk[nd][j][hh] = s * 0.125f;
        }
    }
    __syncwarp();

    // ---- phase 2: eq, ev, ek (sequential stages, low reg peak) ----
    int uA = lane, uB = lane + 32;
    {   // eq
        unsigned long long aq[8];
        unsigned long long b2 = pack2(__ldg(&beq[uA]), __ldg(&beq[uB]));
        #pragma unroll
        for (int j = 0; j < 8; j++) aq[j] = b2;
        #pragma unroll
        for (int c4 = 0; c4 < 4; c4++) {
            float4 wA = __ldg((const float4*)Weq + uA * 4 + c4);
            float4 wB = __ldg((const float4*)Weq + uB * 4 + c4);
            #pragma unroll
            for (int cc = 0; cc < 4; cc++) {
                int c = c4 * 4 + cc;
                unsigned long long w2 = pack2(f4c(wA, cc), f4c(wB, cc));
                #pragma unroll
                for (int j = 0; j < 8; j++) {
                    float f = s_ef[nd][j][c];
                    ffma2(aq[j], pack2(f, f), w2);
                }
            }
        }
        #pragma unroll
        for (int j = 0; j < 8; j++) {
            float2 q2 = unpack2(aq[j]);
            s_eq[nd][j][uA] = q2.x; s_eq[nd][j][uB] = q2.y;
        }
    }
    {   // ev
        unsigned long long av[8];
        unsigned long long b2 = pack2(__ldg(&bev[uA]), __ldg(&bev[uB]));
        #pragma unroll
        for (int j = 0; j < 8; j++) av[j] = b2;
        #pragma unroll
        for (int c4 = 0; c4 < 4; c4++) {
            float4 wA = __ldg((const float4*)Wev + uA * 4 + c4);
            float4 wB = __ldg((const float4*)Wev + uB * 4 + c4);
            #pragma unroll
            for (int cc = 0; cc < 4; cc++) {
                int c = c4 * 4 + cc;
                unsigned long long w2 = pack2(f4c(wA, cc), f4c(wB, cc));
                #pragma unroll
                for (int j = 0; j < 8; j++) {
                    float f = s_ef[nd][j][c];
                    ffma2(av[j], pack2(f, f), w2);
                }
            }
        }
        #pragma unroll
        for (int j = 0; j < 8; j++) {
            float2 v2 = unpack2(av[j]);
            s_ev[nd][j][uA] = v2.x; s_ev[nd][j][uB] = v2.y;
        }
    }
    {   // ek
        unsigned long long ak[8];
        unsigned long long b2 = pack2(__ldg(&bek[uA]), __ldg(&bek[uB]));
        #pragma unroll
        for (int j = 0; j < 8; j++) ak[j] = b2;
        #pragma unroll
        for (int c2 = 0; c2 < 2; c2++) {
            float4 wA = __ldg((const float4*)Wek + uA * 2 + c2);
            float4 wB = __ldg((const float4*)Wek + uB * 2 + c2);
            #pragma unroll
            for (int cc = 0; cc < 4; cc++) {
                int c = c2 * 4 + cc;
                unsigned long long w2 = pack2(f4c(wA, cc), f4c(wB, cc));
                #pragma unroll
                for (int j = 0; j < 8; j++) {
                    float s = s_sqk[nd][j][c];
                    ffma2(ak[j], pack2(s, s), w2);
                }
            }
        }
        #pragma unroll
        for (int j = 0; j < 8; j++) {
            float2 k2 = unpack2(ak[j]);
            s_ek[nd][j][uA] = k2.x; s_ek[nd][j][uB] = k2.y;
        }
    }
    __syncwarp();

    // ---- phase 3: edge-edge attention ----
    #pragma unroll
    for (int rep = 0; rep < 2; rep++) {
        int p = lane + 32 * rep;
        int q = p >> 3, k = p & 7;
        const float4* eqp = (const float4*)&s_eq[nd][q][0];
        const float4* ekp = (const float4*)&s_ek[nd][k][0];
        #pragma unroll
        for (int eh = 0; eh < 4; eh++) {
            float s = 0.f;
            #pragma unroll
            for (int c = 0; c < 4; c++) {
                float4 a = eqp[eh * 4 + c];
                float4 b = ekp[eh * 4 + c];
                s += a.x * b.x + a.y * b.y + a.z * b.z + a.w * b.w;
            }
            s *= 0.25f;
            float mx = s;
            mx = fmaxf(mx, __shfl_xor_sync(0xffffffffu, mx, 1));
            mx = fmaxf(mx, __shfl_xor_sync(0xffffffffu, mx, 2));
            mx = fmaxf(mx, __shfl_xor_sync(0xffffffffu, mx, 4));
            float ex = __expf(s - mx);
            float sm = ex;
            sm += __shfl_xor_sync(0xffffffffu, sm, 1);
            sm += __shfl_xor_sync(0xffffffffu, sm, 2);
            sm += __shfl_xor_sync(0xffffffffu, sm, 4);
            s_att[nd][q][eh][k] = __fdividef(ex, sm + 1e-16f);
        }
    }
    __syncwarp();

    // ---- phase 4: eout ----
    #pragma unroll
    for (int rep = 0; rep < 2; rep++) {
        int u = lane + 32 * rep;
        int eh = u >> 4;
        float evr[8];
        #pragma unroll
        for (int k = 0; k < 8; k++) evr[k] = s_ev[nd][k][u];
        #pragma unroll
        for (int q = 0; q < 8; q++) {
            float4 a0 = *(const float4*)&s_att[nd][q][eh][0];
            float4 a1 = *(const float4*)&s_att[nd][q][eh][4];
            float acc = 0.f;
            acc = fmaf(a0.x, evr[0], acc); acc = fmaf(a0.y, evr[1], acc);
            acc = fmaf(a0.z, evr[2], acc); acc = fmaf(a0.w, evr[3], acc);
            acc = fmaf(a1.x, evr[4], acc); acc = fmaf(a1.y, evr[5], acc);
            acc = fmaf(a1.z, evr[6], acc); acc = fmaf(a1.w, evr[7], acc);
            s_eq[nd][q][u] = acc;
        }
    }
    __syncwarp();

    // ---- phase 5: edge_emb ----
    #pragma unroll
    for (int rep = 0; rep < 2; rep++) {
        int p = lane + 32 * rep;
        int q = p >> 3, h = p & 7;
        float acc = __ldg(&bel[h]);
        const float4* ep = (const float4*)&s_eq[nd][q][0];
        const float4* wp = (const float4*)&s_Wel[h][0];
        #pragma unroll
        for (int c = 0; c < 16; c++) {
            float4 e = ep[c], w = wp[c];
            acc += e.x * w.x + e.y * w.y + e.z * w.z + e.w * w.w;
        }
        s_ee[nd][q][h] = acc;
    }
    __syncwarp();

    // ---- phase 6a: node softmax ----
    if (lane < 8) {
        int h = lane;
        float l[8], mx = -1e30f;
        #pragma unroll
        for (int j = 0; j < 8; j++) {
            l[j] = s_ee[nd][j][h] + s_sqk[nd][j][h];
            mx = fmaxf(mx, l[j]);
        }
        float sm = 0.f;
        #pragma unroll
        for (int j = 0; j < 8; j++) { l[j] = __expf(l[j] - mx); sm += l[j]; }
        float inv = __fdividef(1.f, sm + 1e-16f);
        #pragma unroll
        for (int j = 0; j < 8; j++) s_attn[nd][j][h] = l[j] * inv;
    }
    // ---- phase 6b: edge_embeddings output ----
    #pragma unroll
    for (int rep = 0; rep < 2; rep++) {
        int p = lane + 32 * rep;
        int q = p >> 3, d2 = (p & 7) * 2;
        float a0 = __ldg(&bele[d2]), a1 = __ldg(&bele[d2 + 1]);
        #pragma unroll
        for (int h = 0; h < 8; h++) {
            float e = s_ee[nd][q][h];
            a0 = fmaf(e, s_Wele[d2][h], a0);
            a1 = fmaf(e, s_Wele[d2 + 1][h], a1);
        }
        *(float2*)&out_edge[(n * 8 + q) * 16 + d2] = make_float2(a0, a1);
    }
    __syncwarp();

    // ---- phase 7: node aggregation ----
    #pragma unroll
    for (int i = 0; i < 4; i++) {
        int c4 = lane + 32 * i;
        int h  = c4 >> 4;
        float4 acc = make_float4(0.f, 0.f, 0.f, 0.f);
        #pragma unroll
        for (int j = 0; j < 8; j++) {
            float w = s_attn[nd][j][h];
            float4 v = __ldg((const float4*)(g_nv + (long)e1r[j] * 512) + c4);
            acc.x = fmaf(w, v.x, acc.x); acc.y = fmaf(w, v.y, acc.y);
            acc.z = fmaf(w, v.z, acc.z); acc.w = fmaf(w, v.w, acc.w);
        }
        ((float4*)(g_node + (long)n * 512))[c4] = acc;
    }
}

// ---------------------------------------------------------------------------
// Kernel 3: node_embeddings = g_node[10000,512] @ Wlin^T[512,64] + blin
// ---------------------------------------------------------------------------
__global__ __launch_bounds__(256) void out_gemm_kernel(
    const float* __restrict__ Wlin, const float* __restrict__ blin,
    float* __restrict__ out)
{
    __shared__ float As[64][68];
    __shared__ float Ws[64][66];
    int r0 = blockIdx.x * 64;
    int t  = threadIdx.x;
    int tx = t & 15, ty = t >> 4;
    unsigned long long acc[4][2] = {};

    for (int k0g = 0; k0g < 512; k0g += 64) {
        __syncthreads();
        #pragma unroll
        for (int i = 0; i < 4; i++) {
            int idx = t + i * 256;
            int row = idx >> 4, k4 = idx & 15;
            float4 v = make_float4(0.f, 0.f, 0.f, 0.f);
            if (r0 + row < NN) v = *(const float4*)&g_node[(long)(r0 + row) * 512 + k0g + k4 * 4];
            *(float4*)&As[row][k4 * 4] = v;
            float4 w = *(const float4*)&Wlin[(long)row * 512 + k0g + k4 * 4];
            Ws[k4*4+0][row] = w.x; Ws[k4*4+1][row] = w.y;
            Ws[k4*4+2][row] = w.z; Ws[k4*4+3][row] = w.w;
        }
        __syncthreads();
        #pragma unroll
        for (int k0 = 0; k0 < 64; k0 += 4) {
            float4 a4[4];
            #pragma unroll
            for (int i = 0; i < 4; i++) a4[i] = *(const float4*)&As[ty * 4 + i][k0];
            #pragma unroll
            for (int kk = 0; kk < 4; kk++) {
                unsigned long long b[2];
                #pragma unroll
                for (int p = 0; p < 2; p++)
                    b[p] = *reinterpret_cast<const unsigned long long*>(&Ws[k0 + kk][tx * 2 + 32 * p]);
                #pragma unroll
                for (int i = 0; i < 4; i++) {
                    float av = ((const float*)&a4[i])[kk];
                    unsigned long long a = pack2(av, av);
                    #pragma unroll
                    for (int p = 0; p < 2; p++)
                        ffma2(acc[i][p], a, b[p]);
                }
            }
        }
    }

    #pragma unroll
    for (int i = 0; i < 4; i++) {
        int row = r0 + ty * 4 + i;
        if (row < NN) {
            #pragma unroll
            for (int p = 0; p < 2; p++) {
                int d = tx * 2 + 32 * p;
                float2 r = unpack2(acc[i][p]);
                *(float2*)&out[(long)row * 64 + d] =
                    make_float2(r.x + blin[d], r.y + blin[d + 1]);
            }
        }
    }
}

// ---------------------------------------------------------------------------
extern "C" void kernel_launch(void* const* d_in, const int* in_sizes, int n_in,
                              void* d_out, int out_size)
{
    const float* x    = (const float*)d_in[0];
    const float* ef   = (const float*)d_in[1];
    const float* Wq   = (const float*)d_in[2];
    const float* bq   = (const float*)d_in[3];
    const float* Wk   = (const float*)d_in[4];
    const float* bk   = (const float*)d_in[5];
    const float* Wv   = (const float*)d_in[6];
    const float* bv   = (const float*)d_in[7];
    const float* Wlin = (const float*)d_in[8];
    const float* blin = (const float*)d_in[9];
    const float* Weq  = (const float*)d_in[10];
    const float* beq  = (const float*)d_in[11];
    const float* Wev  = (const float*)d_in[12];
    const float* bev  = (const float*)d_in[13];
    const float* Wek  = (const float*)d_in[14];
    const float* bek  = (const float*)d_in[15];
    const float* Wel  = (const float*)d_in[16];
    const float* bel  = (const float*)d_in[17];
    const float* Wele = (const float*)d_in[18];
    const float* bele = (const float*)d_in[19];
    const int*   eidx = (const int*)d_in[20];
    float* out = (float*)d_out;

    proj_qkv_kernel<<<dim3(12, 157), 128>>>(x, Wq, bq, Wk, bk, Wv, bv);
    node_edge_kernel<<<NN / 4, 128>>>(ef, eidx, Weq, beq, Wev, bev, Wek, bek,
                                      Wel, bel, Wele, bele, out + NN * 64);
    out_gemm_kernel<<<157, 256>>>(Wlin, blin, out);
}

// round 15
// speedup vs baseline: 1.1592x; 1.1592x over previous
#include <cuda_runtime.h>
#include <cstdint>

#define NN 10000     // nodes
#define KD 8         // out-degree
#define EE 80000     // edges
#define HDIM 512     // H*D

// Scratch (allocation-free rule: __device__ globals)
__device__ float g_nq[NN * HDIM];
__device__ float g_nk[NN * HDIM];
__device__ float g_nv[NN * HDIM];
__device__ float g_node[NN * HDIM];

// ---- packed f32x2 helpers ----
__device__ __forceinline__ unsigned long long pack2(float lo, float hi) {
    unsigned long long r;
    asm("mov.b64 %0, {%1, %2};" : "=l"(r) : "f"(lo), "f"(hi));
    return r;
}
__device__ __forceinline__ void ffma2(unsigned long long& d,
                                      unsigned long long a,
                                      unsigned long long b) {
    asm("fma.rn.f32x2 %0, %1, %2, %0;" : "+l"(d) : "l"(a), "l"(b));
}
__device__ __forceinline__ float2 unpack2(unsigned long long v) {
    float2 f;
    asm("mov.b64 {%0, %1}, %2;" : "=f"(f.x), "=f"(f.y) : "l"(v));
    return f;
}
__device__ __forceinline__ float f4c(const float4& v, int i) {
    return (i == 0) ? v.x : (i == 1) ? v.y : (i == 2) ? v.z : v.w;
}
__device__ __forceinline__ uint32_t to_tf32(float f) {
    uint32_t r;
    asm("cvt.rna.tf32.f32 %0, %1;" : "=r"(r) : "f"(f));
    return r;
}
__device__ __forceinline__ void mma_tf32(float4& d,
                                         uint32_t a0, uint32_t a1, uint32_t a2, uint32_t a3,
                                         uint32_t b0, uint32_t b1) {
    asm("mma.sync.aligned.m16n8k8.row.col.f32.tf32.tf32.f32 "
        "{%0,%1,%2,%3}, {%4,%5,%6,%7}, {%8,%9}, {%0,%1,%2,%3};"
        : "+f"(d.x), "+f"(d.y), "+f"(d.z), "+f"(d.w)
        : "r"(a0), "r"(a1), "r"(a2), "r"(a3), "r"(b0), "r"(b1));
}

// ---------------------------------------------------------------------------
// Kernel 1: fused QKV projection, tensor pipe (tf32 mma.sync).
// Block: 128 threads (4 warps), tile 64 rows x 128 cols, K=64.
// BOTH operands staged in [row/col][k] layout (pad 68): conflict-free float4
// staging AND conflict-free fragment loads (bank = 4g+tg + const).
// ---------------------------------------------------------------------------
__global__ __launch_bounds__(128) void proj_qkv_kernel(
    const float* __restrict__ X,
    const float* __restrict__ Wq, const float* __restrict__ bq,
    const float* __restrict__ Wk, const float* __restrict__ bk,
    const float* __restrict__ Wv, const float* __restrict__ bv)
{
    __shared__ uint32_t As[64][68];    // [row][k]  tf32 bits
    __shared__ uint32_t Bs[128][68];   // [col][k]  tf32 bits (NO transpose)

    int bx  = blockIdx.x;
    int sel = bx >> 2;
    int c0  = (bx & 3) * 128;
    int r0  = blockIdx.y * 64;
    int t   = threadIdx.x;

    const float* W    = (sel == 0) ? Wq : (sel == 1) ? Wk : Wv;
    const float* bias = (sel == 0) ? bq : (sel == 1) ? bk : bv;
    float*       outp = (sel == 0) ? g_nq : (sel == 1) ? g_nk : g_nv;

    // stage X tile (64 rows x 64 k) as tf32 — conflict-free float4-ish stores
    #pragma unroll
    for (int i = 0; i < 8; i++) {
        int idx = t + i * 128;
        int row = idx >> 4, k4 = idx & 15;
        float4 v = make_float4(0.f, 0.f, 0.f, 0.f);
        if (r0 + row < NN) v = *(const float4*)&X[(r0 + row) * 64 + k4 * 4];
        uint4 u = make_uint4(to_tf32(v.x), to_tf32(v.y), to_tf32(v.z), to_tf32(v.w));
        *(uint4*)&As[row][k4 * 4] = u;
    }
    // stage W tile (128 cols x 64 k) as tf32, [col][k] — conflict-free
    #pragma unroll
    for (int i = 0; i < 16; i++) {
        int idx = t + i * 128;
        int c = idx >> 4, k4 = idx & 15;
        float4 w = *(const float4*)&W[(c0 + c) * 64 + k4 * 4];
        uint4 u = make_uint4(to_tf32(w.x), to_tf32(w.y), to_tf32(w.z), to_tf32(w.w));
        *(uint4*)&Bs[c][k4 * 4] = u;
    }
    __syncthreads();

    int warp = t >> 5, lane = t & 31;
    int g  = lane >> 2;      // groupID (0..7)
    int tg = lane & 3;       // thread-in-group (0..3)
    int mrow = warp * 16;

    float4 acc[16];
    #pragma unroll
    for (int i = 0; i < 16; i++) acc[i] = make_float4(0.f, 0.f, 0.f, 0.f);

    #pragma unroll
    for (int ks = 0; ks < 8; ks++) {
        int k0 = ks * 8;
        uint32_t a0 = As[mrow + g][k0 + tg];
        uint32_t a1 = As[mrow + g + 8][k0 + tg];
        uint32_t a2 = As[mrow + g][k0 + tg + 4];
        uint32_t a3 = As[mrow + g + 8][k0 + tg + 4];
        #pragma unroll
        for (int nt = 0; nt < 16; nt++) {
            int n0 = nt * 8;
            uint32_t b0 = Bs[n0 + g][k0 + tg];        // B col-major: [n][k]
            uint32_t b1 = Bs[n0 + g][k0 + tg + 4];
            mma_tf32(acc[nt], a0, a1, a2, a3, b0, b1);
        }
    }

    // epilogue: thread owns (rows mrow+g, mrow+g+8) x (cols 2*tg, 2*tg+1)
    int row1 = r0 + mrow + g;
    int row2 = row1 + 8;
    bool ok1 = row1 < NN, ok2 = row2 < NN;
    #pragma unroll
    for (int nt = 0; nt < 16; nt++) {
        int n = c0 + nt * 8 + 2 * tg;
        float2 b2 = *(const float2*)&bias[n];
        if (ok1) *(float2*)&outp[(long)row1 * HDIM + n] =
            make_float2(acc[nt].x + b2.x, acc[nt].y + b2.y);
        if (ok2) *(float2*)&outp[(long)row2 * HDIM + n] =
            make_float2(acc[nt].z + b2.x, acc[nt].w + b2.y);
    }
}

// ---------------------------------------------------------------------------
// Kernel 2: warp-per-node fused pipeline (exact R11 version — best known).
// ---------------------------------------------------------------------------
__global__ __launch_bounds__(128) void node_edge_kernel(
    const float* __restrict__ edge_features,
    const int*   __restrict__ edge_index,
    const float* __restrict__ Weq, const float* __restrict__ beq,
    const float* __restrict__ Wev, const float* __restrict__ bev,
    const float* __restrict__ Wek, const float* __restrict__ bek,
    const float* __restrict__ Wel, const float* __restrict__ bel,
    const float* __restrict__ Wele, const float* __restrict__ bele,
    float* __restrict__ out_edge)
{
    __shared__ __align__(16) float s_Wel[8][68];  // [h][c]
    __shared__ float s_Wele[16][9];               // [de][h]
    __shared__ __align__(16) float s_ef[4][8][16];
    __shared__ __align__(16) float s_eq[4][8][68];   // eq, reused as eout
    __shared__ __align__(16) float s_ev[4][8][68];
    __shared__ __align__(16) float s_ek[4][8][68];
    __shared__ __align__(16) float s_att[4][8][4][8];
    __shared__ float s_sqk[4][8][8];
    __shared__ float s_ee[4][8][8];
    __shared__ float s_attn[4][8][8];

    int t    = threadIdx.x;
    int nd   = t >> 5;
    int lane = t & 31;
    int n    = blockIdx.x * 4 + nd;

    for (int i = t; i < 512; i += 128) s_Wel[i >> 6][i & 63] = Wel[i];
    s_Wele[t >> 3][t & 7] = Wele[t];
    __syncthreads();

    int ej = (lane < 8) ? edge_index[EE + n * 8 + lane] : 0;
    int e1r[8];
    #pragma unroll
    for (int j = 0; j < 8; j++) e1r[j] = __shfl_sync(0xffffffffu, ej, j);

    ((float4*)&s_ef[nd][0][0])[lane] =
        ((const float4*)(edge_features + (long)n * 128))[lane];

    // ---- phase 1: sqk head-aligned ----
    {
        int hh = lane >> 2, mm = lane & 3;
        const float4* qp = (const float4*)(g_nq + (long)n * 512);
        float4 q4[4];
        #pragma unroll
        for (int i = 0; i < 4; i++) q4[i] = qp[hh * 16 + mm + 4 * i];
        #pragma unroll
        for (int j = 0; j < 8; j++) {
            const float4* kp = (const float4*)(g_nk + (long)e1r[j] * 512);
            float s = 0.f;
            #pragma unroll
            for (int i = 0; i < 4; i++) {
                float4 kv = __ldg(&kp[hh * 16 + mm + 4 * i]);
                s += q4[i].x * kv.x + q4[i].y * kv.y + q4[i].z * kv.z + q4[i].w * kv.w;
            }
            s += __shfl_xor_sync(0xffffffffu, s, 1);
            s += __shfl_xor_sync(0xffffffffu, s, 2);
            if (mm == 0) s_sqk[nd][j][hh] = s * 0.125f;
        }
    }
    __syncwarp();

    // ---- phase 2: eq, ev, ek (sequential stages, low reg peak) ----
    int uA = lane, uB = lane + 32;
    {   // eq
        unsigned long long aq[8];
        unsigned long long b2 = pack2(__ldg(&beq[uA]), __ldg(&beq[uB]));
        #pragma unroll
        for (int j = 0; j < 8; j++) aq[j] = b2;
        #pragma unroll
        for (int c4 = 0; c4 < 4; c4++) {
            float4 wA = __ldg((const float4*)Weq + uA * 4 + c4);
            float4 wB = __ldg((const float4*)Weq + uB * 4 + c4);
            #pragma unroll
            for (int cc = 0; cc < 4; cc++) {
                int c = c4 * 4 + cc;
                unsigned long long w2 = pack2(f4c(wA, cc), f4c(wB, cc));
                #pragma unroll
                for (int j = 0; j < 8; j++) {
                    float f = s_ef[nd][j][c];
                    ffma2(aq[j], pack2(f, f), w2);
                }
            }
        }
        #pragma unroll
        for (int j = 0; j < 8; j++) {
            float2 q2 = unpack2(aq[j]);
            s_eq[nd][j][uA] = q2.x; s_eq[nd][j][uB] = q2.y;
        }
    }
    {   // ev
        unsigned long long av[8];
        unsigned long long b2 = pack2(__ldg(&bev[uA]), __ldg(&bev[uB]));
        #pragma unroll
        for (int j = 0; j < 8; j++) av[j] = b2;
        #pragma unroll
        for (int c4 = 0; c4 < 4; c4++) {
            float4 wA = __ldg((const float4*)Wev + uA * 4 + c4);
            float4 wB = __ldg((const float4*)Wev + uB * 4 + c4);
            #pragma unroll
            for (int cc = 0; cc < 4; cc++) {
                int c = c4 * 4 + cc;
                unsigned long long w2 = pack2(f4c(wA, cc), f4c(wB, cc));
                #pragma unroll
                for (int j = 0; j < 8; j++) {
                    float f = s_ef[nd][j][c];
                    ffma2(av[j], pack2(f, f), w2);
                }
            }
        }
        #pragma unroll
        for (int j = 0; j < 8; j++) {
            float2 v2 = unpack2(av[j]);
            s_ev[nd][j][uA] = v2.x; s_ev[nd][j][uB] = v2.y;
        }
    }
    {   // ek
        unsigned long long ak[8];
        unsigned long long b2 = pack2(__ldg(&bek[uA]), __ldg(&bek[uB]));
        #pragma unroll
        for (int j = 0; j < 8; j++) ak[j] = b2;
        #pragma unroll
        for (int c2 = 0; c2 < 2; c2++) {
            float4 wA = __ldg((const float4*)Wek + uA * 2 + c2);
            float4 wB = __ldg((const float4*)Wek + uB * 2 + c2);
            #pragma unroll
            for (int cc = 0; cc < 4; cc++) {
                int c = c2 * 4 + cc;
                unsigned long long w2 = pack2(f4c(wA, cc), f4c(wB, cc));
                #pragma unroll
                for (int j = 0; j < 8; j++) {
                    float s = s_sqk[nd][j][c];
                    ffma2(ak[j], pack2(s, s), w2);
                }
            }
        }
        #pragma unroll
        for (int j = 0; j < 8; j++) {
            float2 k2 = unpack2(ak[j]);
            s_ek[nd][j][uA] = k2.x; s_ek[nd][j][uB] = k2.y;
        }
    }
    __syncwarp();

    // ---- phase 3: edge-edge attention ----
    #pragma unroll
    for (int rep = 0; rep < 2; rep++) {
        int p = lane + 32 * rep;
        int q = p >> 3, k = p & 7;
        const float4* eqp = (const float4*)&s_eq[nd][q][0];
        const float4* ekp = (const float4*)&s_ek[nd][k][0];
        #pragma unroll
        for (int eh = 0; eh < 4; eh++) {
            float s = 0.f;
            #pragma unroll
            for (int c = 0; c < 4; c++) {
                float4 a = eqp[eh * 4 + c];
                float4 b = ekp[eh * 4 + c];
                s += a.x * b.x + a.y * b.y + a.z * b.z + a.w * b.w;
            }
            s *= 0.25f;
            float mx = s;
            mx = fmaxf(mx, __shfl_xor_sync(0xffffffffu, mx, 1));
            mx = fmaxf(mx, __shfl_xor_sync(0xffffffffu, mx, 2));
            mx = fmaxf(mx, __shfl_xor_sync(0xffffffffu, mx, 4));
            float ex = __expf(s - mx);
            float sm = ex;
            sm += __shfl_xor_sync(0xffffffffu, sm, 1);
            sm += __shfl_xor_sync(0xffffffffu, sm, 2);
            sm += __shfl_xor_sync(0xffffffffu, sm, 4);
            s_att[nd][q][eh][k] = __fdividef(ex, sm + 1e-16f);
        }
    }
    __syncwarp();

    // ---- phase 4: eout ----
    #pragma unroll
    for (int rep = 0; rep < 2; rep++) {
        int u = lane + 32 * rep;
        int eh = u >> 4;
        float evr[8];
        #pragma unroll
        for (int k = 0; k < 8; k++) evr[k] = s_ev[nd][k][u];
        #pragma unroll
        for (int q = 0; q < 8; q++) {
            float4 a0 = *(const float4*)&s_att[nd][q][eh][0];
            float4 a1 = *(const float4*)&s_att[nd][q][eh][4];
            float acc = 0.f;
            acc = fmaf(a0.x, evr[0], acc); acc = fmaf(a0.y, evr[1], acc);
            acc = fmaf(a0.z, evr[2], acc); acc = fmaf(a0.w, evr[3], acc);
            acc = fmaf(a1.x, evr[4], acc); acc = fmaf(a1.y, evr[5], acc);
            acc = fmaf(a1.z, evr[6], acc); acc = fmaf(a1.w, evr[7], acc);
            s_eq[nd][q][u] = acc;
        }
    }
    __syncwarp();

    // ---- phase 5: edge_emb ----
    #pragma unroll
    for (int rep = 0; rep < 2; rep++) {
        int p = lane + 32 * rep;
        int q = p >> 3, h = p & 7;
        float acc = __ldg(&bel[h]);
        const float4* ep = (const float4*)&s_eq[nd][q][0];
        const float4* wp = (const float4*)&s_Wel[h][0];
        #pragma unroll
        for (int c = 0; c < 16; c++) {
            float4 e = ep[c], w = wp[c];
            acc += e.x * w.x + e.y * w.y + e.z * w.z + e.w * w.w;
        }
        s_ee[nd][q][h] = acc;
    }
    __syncwarp();

    // ---- phase 6a: node softmax ----
    if (lane < 8) {
        int h = lane;
        float l[8], mx = -1e30f;
        #pragma unroll
        for (int j = 0; j < 8; j++) {
            l[j] = s_ee[nd][j][h] + s_sqk[nd][j][h];
            mx = fmaxf(mx, l[j]);
        }
        float sm = 0.f;
        #pragma unroll
        for (int j = 0; j < 8; j++) { l[j] = __expf(l[j] - mx); sm += l[j]; }
        float inv = __fdividef(1.f, sm + 1e-16f);
        #pragma unroll
        for (int j = 0; j < 8; j++) s_attn[nd][j][h] = l[j] * inv;
    }
    // ---- phase 6b: edge_embeddings output ----
    #pragma unroll
    for (int rep = 0; rep < 2; rep++) {
        int p = lane + 32 * rep;
        int q = p >> 3, d2 = (p & 7) * 2;
        float a0 = __ldg(&bele[d2]), a1 = __ldg(&bele[d2 + 1]);
        #pragma unroll
        for (int h = 0; h < 8; h++) {
            float e = s_ee[nd][q][h];
            a0 = fmaf(e, s_Wele[d2][h], a0);
            a1 = fmaf(e, s_Wele[d2 + 1][h], a1);
        }
        *(float2*)&out_edge[(n * 8 + q) * 16 + d2] = make_float2(a0, a1);
    }
    __syncwarp();

    // ---- phase 7: node aggregation ----
    #pragma unroll
    for (int i = 0; i < 4; i++) {
        int c4 = lane + 32 * i;
        int h  = c4 >> 4;
        float4 acc = make_float4(0.f, 0.f, 0.f, 0.f);
        #pragma unroll
        for (int j = 0; j < 8; j++) {
            float w = s_attn[nd][j][h];
            float4 v = __ldg((const float4*)(g_nv + (long)e1r[j] * 512) + c4);
            acc.x = fmaf(w, v.x, acc.x); acc.y = fmaf(w, v.y, acc.y);
            acc.z = fmaf(w, v.z, acc.z); acc.w = fmaf(w, v.w, acc.w);
        }
        ((float4*)(g_node + (long)n * 512))[c4] = acc;
    }
}

// ---------------------------------------------------------------------------
// Kernel 3: node_embeddings = g_node[10000,512] @ Wlin^T[512,64] + blin
// ---------------------------------------------------------------------------
__global__ __launch_bounds__(256) void out_gemm_kernel(
    const float* __restrict__ Wlin, const float* __restrict__ blin,
    float* __restrict__ out)
{
    __shared__ float As[64][68];
    __shared__ float Ws[64][66];
    int r0 = blockIdx.x * 64;
    int t  = threadIdx.x;
    int tx = t & 15, ty = t >> 4;
    unsigned long long acc[4][2] = {};

    for (int k0g = 0; k0g < 512; k0g += 64) {
        __syncthreads();
        #pragma unroll
        for (int i = 0; i < 4; i++) {
            int idx = t + i * 256;
            int row = idx >> 4, k4 = idx & 15;
            float4 v = make_float4(0.f, 0.f, 0.f, 0.f);
            if (r0 + row < NN) v = *(const float4*)&g_node[(long)(r0 + row) * 512 + k0g + k4 * 4];
            *(float4*)&As[row][k4 * 4] = v;
            float4 w = *(const float4*)&Wlin[(long)row * 512 + k0g + k4 * 4];
            Ws[k4*4+0][row] = w.x; Ws[k4*4+1][row] = w.y;
            Ws[k4*4+2][row] = w.z; Ws[k4*4+3][row] = w.w;
        }
        __syncthreads();
        #pragma unroll
        for (int k0 = 0; k0 < 64; k0 += 4) {
            float4 a4[4];
            #pragma unroll
            for (int i = 0; i < 4; i++) a4[i] = *(const float4*)&As[ty * 4 + i][k0];
            #pragma unroll
            for (int kk = 0; kk < 4; kk++) {
                unsigned long long b[2];
                #pragma unroll
                for (int p = 0; p < 2; p++)
                    b[p] = *reinterpret_cast<const unsigned long long*>(&Ws[k0 + kk][tx * 2 + 32 * p]);
                #pragma unroll
                for (int i = 0; i < 4; i++) {
                    float av = ((const float*)&a4[i])[kk];
                    unsigned long long a = pack2(av, av);
                    #pragma unroll
                    for (int p = 0; p < 2; p++)
                        ffma2(acc[i][p], a, b[p]);
                }
            }
        }
    }

    #pragma unroll
    for (int i = 0; i < 4; i++) {
        int row = r0 + ty * 4 + i;
        if (row < NN) {
            #pragma unroll
            for (int p = 0; p < 2; p++) {
                int d = tx * 2 + 32 * p;
                float2 r = unpack2(acc[i][p]);
                *(float2*)&out[(long)row * 64 + d] =
                    make_float2(r.x + blin[d], r.y + blin[d + 1]);
            }
        }
    }
}

// ---------------------------------------------------------------------------
extern "C" void kernel_launch(void* const* d_in, const int* in_sizes, int n_in,
                              void* d_out, int out_size)
{
    const float* x    = (const float*)d_in[0];
    const float* ef   = (const float*)d_in[1];
    const float* Wq   = (const float*)d_in[2];
    const float* bq   = (const float*)d_in[3];
    const float* Wk   = (const float*)d_in[4];
    const float* bk   = (const float*)d_in[5];
    const float* Wv   = (const float*)d_in[6];
    const float* bv   = (const float*)d_in[7];
    const float* Wlin = (const float*)d_in[8];
    const float* blin = (const float*)d_in[9];
    const float* Weq  = (const float*)d_in[10];
    const float* beq  = (const float*)d_in[11];
    const float* Wev  = (const float*)d_in[12];
    const float* bev  = (const float*)d_in[13];
    const float* Wek  = (const float*)d_in[14];
    const float* bek  = (const float*)d_in[15];
    const float* Wel  = (const float*)d_in[16];
    const float* bel  = (const float*)d_in[17];
    const float* Wele = (const float*)d_in[18];
    const float* bele = (const float*)d_in[19];
    const int*   eidx = (const int*)d_in[20];
    float* out = (float*)d_out;

    proj_qkv_kernel<<<dim3(12, 157), 128>>>(x, Wq, bq, Wk, bk, Wv, bv);
    node_edge_kernel<<<NN / 4, 128>>>(ef, eidx, Weq, beq, Wev, bev, Wek, bek,
                                      Wel, bel, Wele, bele, out + NN * 64);
    out_gemm_kernel<<<157, 256>>>(Wlin, blin, out);
}

// round 16
// speedup vs baseline: 1.2057x; 1.0401x over previous
#include <cuda_runtime.h>
#include <cstdint>

#define NN 10000     // nodes
#define KD 8         // out-degree
#define EE 80000     // edges
#define HDIM 512     // H*D

// Scratch (allocation-free rule: __device__ globals)
__device__ float g_nq[NN * HDIM];
__device__ float g_nk[NN * HDIM];
__device__ float g_nv[NN * HDIM];
__device__ float g_node[NN * HDIM];

// ---- packed f32x2 helpers ----
__device__ __forceinline__ unsigned long long pack2(float lo, float hi) {
    unsigned long long r;
    asm("mov.b64 %0, {%1, %2};" : "=l"(r) : "f"(lo), "f"(hi));
    return r;
}
__device__ __forceinline__ void ffma2(unsigned long long& d,
                                      unsigned long long a,
                                      unsigned long long b) {
    asm("fma.rn.f32x2 %0, %1, %2, %0;" : "+l"(d) : "l"(a), "l"(b));
}
__device__ __forceinline__ float2 unpack2(unsigned long long v) {
    float2 f;
    asm("mov.b64 {%0, %1}, %2;" : "=f"(f.x), "=f"(f.y) : "l"(v));
    return f;
}
__device__ __forceinline__ float f4c(const float4& v, int i) {
    return (i == 0) ? v.x : (i == 1) ? v.y : (i == 2) ? v.z : v.w;
}
__device__ __forceinline__ uint32_t to_tf32(float f) {
    uint32_t r;
    asm("cvt.rna.tf32.f32 %0, %1;" : "=r"(r) : "f"(f));
    return r;
}
__device__ __forceinline__ void mma_tf32(float4& d,
                                         uint32_t a0, uint32_t a1, uint32_t a2, uint32_t a3,
                                         uint32_t b0, uint32_t b1) {
    asm("mma.sync.aligned.m16n8k8.row.col.f32.tf32.tf32.f32 "
        "{%0,%1,%2,%3}, {%4,%5,%6,%7}, {%8,%9}, {%0,%1,%2,%3};"
        : "+f"(d.x), "+f"(d.y), "+f"(d.z), "+f"(d.w)
        : "r"(a0), "r"(a1), "r"(a2), "r"(a3), "r"(b0), "r"(b1));
}

// ---------------------------------------------------------------------------
// Kernel 1: fused QKV projection, tensor pipe (tf32 mma.sync).
// Block: 128 threads (4 warps), tile 64 rows x 128 cols, K=64.
// Warp-split along N: warp owns ALL 4 m-tiles x 4 n-tiles (cols w*32..+32):
// per k-step 16 A-LDS + 8 B-LDS per 16 HMMA (vs 36 LDS with m-split).
// ---------------------------------------------------------------------------
__global__ __launch_bounds__(128) void proj_qkv_kernel(
    const float* __restrict__ X,
    const float* __restrict__ Wq, const float* __restrict__ bq,
    const float* __restrict__ Wk, const float* __restrict__ bk,
    const float* __restrict__ Wv, const float* __restrict__ bv)
{
    __shared__ uint32_t As[64][68];    // [row][k]  tf32 bits
    __shared__ uint32_t Bs[128][68];   // [col][k]  tf32 bits

    int bx  = blockIdx.x;
    int sel = bx >> 2;
    int c0  = (bx & 3) * 128;
    int r0  = blockIdx.y * 64;
    int t   = threadIdx.x;

    const float* W    = (sel == 0) ? Wq : (sel == 1) ? Wk : Wv;
    const float* bias = (sel == 0) ? bq : (sel == 1) ? bk : bv;
    float*       outp = (sel == 0) ? g_nq : (sel == 1) ? g_nk : g_nv;

    #pragma unroll
    for (int i = 0; i < 8; i++) {
        int idx = t + i * 128;
        int row = idx >> 4, k4 = idx & 15;
        float4 v = make_float4(0.f, 0.f, 0.f, 0.f);
        if (r0 + row < NN) v = *(const float4*)&X[(r0 + row) * 64 + k4 * 4];
        uint4 u = make_uint4(to_tf32(v.x), to_tf32(v.y), to_tf32(v.z), to_tf32(v.w));
        *(uint4*)&As[row][k4 * 4] = u;
    }
    #pragma unroll
    for (int i = 0; i < 16; i++) {
        int idx = t + i * 128;
        int c = idx >> 4, k4 = idx & 15;
        float4 w = *(const float4*)&W[(c0 + c) * 64 + k4 * 4];
        uint4 u = make_uint4(to_tf32(w.x), to_tf32(w.y), to_tf32(w.z), to_tf32(w.w));
        *(uint4*)&Bs[c][k4 * 4] = u;
    }
    __syncthreads();

    int warp = t >> 5, lane = t & 31;
    int g  = lane >> 2;      // groupID (0..7)
    int tg = lane & 3;       // thread-in-group (0..3)
    int nbase = warp * 32;   // warp's 32-col slice

    float4 acc[4][4];        // [m-tile][n-tile]
    #pragma unroll
    for (int i = 0; i < 4; i++)
        #pragma unroll
        for (int j = 0; j < 4; j++) acc[i][j] = make_float4(0.f, 0.f, 0.f, 0.f);

    #pragma unroll
    for (int ks = 0; ks < 8; ks++) {
        int k0 = ks * 8;
        uint32_t a0[4], a1[4], a2[4], a3[4];
        #pragma unroll
        for (int mt = 0; mt < 4; mt++) {
            int mr = mt * 16;
            a0[mt] = As[mr + g][k0 + tg];
            a1[mt] = As[mr + g + 8][k0 + tg];
            a2[mt] = As[mr + g][k0 + tg + 4];
            a3[mt] = As[mr + g + 8][k0 + tg + 4];
        }
        #pragma unroll
        for (int nt = 0; nt < 4; nt++) {
            int n0 = nbase + nt * 8;
            uint32_t b0 = Bs[n0 + g][k0 + tg];
            uint32_t b1 = Bs[n0 + g][k0 + tg + 4];
            #pragma unroll
            for (int mt = 0; mt < 4; mt++)
                mma_tf32(acc[mt][nt], a0[mt], a1[mt], a2[mt], a3[mt], b0, b1);
        }
    }

    #pragma unroll
    for (int mt = 0; mt < 4; mt++) {
        int row1 = r0 + mt * 16 + g;
        int row2 = row1 + 8;
        bool ok1 = row1 < NN, ok2 = row2 < NN;
        #pragma unroll
        for (int nt = 0; nt < 4; nt++) {
            int n = c0 + nbase + nt * 8 + 2 * tg;
            float2 b2 = *(const float2*)&bias[n];
            if (ok1) *(float2*)&outp[(long)row1 * HDIM + n] =
                make_float2(acc[mt][nt].x + b2.x, acc[mt][nt].y + b2.y);
            if (ok2) *(float2*)&outp[(long)row2 * HDIM + n] =
                make_float2(acc[mt][nt].z + b2.x, acc[mt][nt].w + b2.y);
        }
    }
}

// ---------------------------------------------------------------------------
// Kernel 2: warp-per-node fused pipeline (exact R11 version — best known).
// ---------------------------------------------------------------------------
__global__ __launch_bounds__(128) void node_edge_kernel(
    const float* __restrict__ edge_features,
    const int*   __restrict__ edge_index,
    const float* __restrict__ Weq, const float* __restrict__ beq,
    const float* __restrict__ Wev, const float* __restrict__ bev,
    const float* __restrict__ Wek, const float* __restrict__ bek,
    const float* __restrict__ Wel, const float* __restrict__ bel,
    const float* __restrict__ Wele, const float* __restrict__ bele,
    float* __restrict__ out_edge)
{
    __shared__ __align__(16) float s_Wel[8][68];  // [h][c]
    __shared__ float s_Wele[16][9];               // [de][h]
    __shared__ __align__(16) float s_ef[4][8][16];
    __shared__ __align__(16) float s_eq[4][8][68];   // eq, reused as eout
    __shared__ __align__(16) float s_ev[4][8][68];
    __shared__ __align__(16) float s_ek[4][8][68];
    __shared__ __align__(16) float s_att[4][8][4][8];
    __shared__ float s_sqk[4][8][8];
    __shared__ float s_ee[4][8][8];
    __shared__ float s_attn[4][8][8];

    int t    = threadIdx.x;
    int nd   = t >> 5;
    int lane = t & 31;
    int n    = blockIdx.x * 4 + nd;

    for (int i = t; i < 512; i += 128) s_Wel[i >> 6][i & 63] = Wel[i];
    s_Wele[t >> 3][t & 7] = Wele[t];
    __syncthreads();

    int ej = (lane < 8) ? edge_index[EE + n * 8 + lane] : 0;
    int e1r[8];
    #pragma unroll
    for (int j = 0; j < 8; j++) e1r[j] = __shfl_sync(0xffffffffu, ej, j);

    ((float4*)&s_ef[nd][0][0])[lane] =
        ((const float4*)(edge_features + (long)n * 128))[lane];

    // ---- phase 1: sqk head-aligned ----
    {
        int hh = lane >> 2, mm = lane & 3;
        const float4* qp = (const float4*)(g_nq + (long)n * 512);
        float4 q4[4];
        #pragma unroll
        for (int i = 0; i < 4; i++) q4[i] = qp[hh * 16 + mm + 4 * i];
        #pragma unroll
        for (int j = 0; j < 8; j++) {
            const float4* kp = (const float4*)(g_nk + (long)e1r[j] * 512);
            float s = 0.f;
            #pragma unroll
            for (int i = 0; i < 4; i++) {
                float4 kv = __ldg(&kp[hh * 16 + mm + 4 * i]);
                s += q4[i].x * kv.x + q4[i].y * kv.y + q4[i].z * kv.z + q4[i].w * kv.w;
            }
            s += __shfl_xor_sync(0xffffffffu, s, 1);
            s += __shfl_xor_sync(0xffffffffu, s, 2);
            if (mm == 0) s_sqk[nd][j][hh] = s * 0.125f;
        }
    }
    __syncwarp();

    // ---- phase 2: eq, ev, ek (sequential stages, low reg peak) ----
    int uA = lane, uB = lane + 32;
    {   // eq
        unsigned long long aq[8];
        unsigned long long b2 = pack2(__ldg(&beq[uA]), __ldg(&beq[uB]));
        #pragma unroll
        for (int j = 0; j < 8; j++) aq[j] = b2;
        #pragma unroll
        for (int c4 = 0; c4 < 4; c4++) {
            float4 wA = __ldg((const float4*)Weq + uA * 4 + c4);
            float4 wB = __ldg((const float4*)Weq + uB * 4 + c4);
            #pragma unroll
            for (int cc = 0; cc < 4; cc++) {
                int c = c4 * 4 + cc;
                unsigned long long w2 = pack2(f4c(wA, cc), f4c(wB, cc));
                #pragma unroll
                for (int j = 0; j < 8; j++) {
                    float f = s_ef[nd][j][c];
                    ffma2(aq[j], pack2(f, f), w2);
                }
            }
        }
        #pragma unroll
        for (int j = 0; j < 8; j++) {
            float2 q2 = unpack2(aq[j]);
            s_eq[nd][j][uA] = q2.x; s_eq[nd][j][uB] = q2.y;
        }
    }
    {   // ev
        unsigned long long av[8];
        unsigned long long b2 = pack2(__ldg(&bev[uA]), __ldg(&bev[uB]));
        #pragma unroll
        for (int j = 0; j < 8; j++) av[j] = b2;
        #pragma unroll
        for (int c4 = 0; c4 < 4; c4++) {
            float4 wA = __ldg((const float4*)Wev + uA * 4 + c4);
            float4 wB = __ldg((const float4*)Wev + uB * 4 + c4);
            #pragma unroll
            for (int cc = 0; cc < 4; cc++) {
                int c = c4 * 4 + cc;
                unsigned long long w2 = pack2(f4c(wA, cc), f4c(wB, cc));
                #pragma unroll
                for (int j = 0; j < 8; j++) {
                    float f = s_ef[nd][j][c];
                    ffma2(av[j], pack2(f, f), w2);
                }
            }
        }
        #pragma unroll
        for (int j = 0; j < 8; j++) {
            float2 v2 = unpack2(av[j]);
            s_ev[nd][j][uA] = v2.x; s_ev[nd][j][uB] = v2.y;
        }
    }
    {   // ek
        unsigned long long ak[8];
        unsigned long long b2 = pack2(__ldg(&bek[uA]), __ldg(&bek[uB]));
        #pragma unroll
        for (int j = 0; j < 8; j++) ak[j] = b2;
        #pragma unroll
        for (int c2 = 0; c2 < 2; c2++) {
            float4 wA = __ldg((const float4*)Wek + uA * 2 + c2);
            float4 wB = __ldg((const float4*)Wek + uB * 2 + c2);
            #pragma unroll
            for (int cc = 0; cc < 4; cc++) {
                int c = c2 * 4 + cc;
                unsigned long long w2 = pack2(f4c(wA, cc), f4c(wB, cc));
                #pragma unroll
                for (int j = 0; j < 8; j++) {
                    float s = s_sqk[nd][j][c];
                    ffma2(ak[j], pack2(s, s), w2);
                }
            }
        }
        #pragma unroll
        for (int j = 0; j < 8; j++) {
            float2 k2 = unpack2(ak[j]);
            s_ek[nd][j][uA] = k2.x; s_ek[nd][j][uB] = k2.y;
        }
    }
    __syncwarp();

    // ---- phase 3: edge-edge attention ----
    #pragma unroll
    for (int rep = 0; rep < 2; rep++) {
        int p = lane + 32 * rep;
        int q = p >> 3, k = p & 7;
        const float4* eqp = (const float4*)&s_eq[nd][q][0];
        const float4* ekp = (const float4*)&s_ek[nd][k][0];
        #pragma unroll
        for (int eh = 0; eh < 4; eh++) {
            float s = 0.f;
            #pragma unroll
            for (int c = 0; c < 4; c++) {
                float4 a = eqp[eh * 4 + c];
                float4 b = ekp[eh * 4 + c];
                s += a.x * b.x + a.y * b.y + a.z * b.z + a.w * b.w;
            }
            s *= 0.25f;
            float mx = s;
            mx = fmaxf(mx, __shfl_xor_sync(0xffffffffu, mx, 1));
            mx = fmaxf(mx, __shfl_xor_sync(0xffffffffu, mx, 2));
            mx = fmaxf(mx, __shfl_xor_sync(0xffffffffu, mx, 4));
            float ex = __expf(s - mx);
            float sm = ex;
            sm += __shfl_xor_sync(0xffffffffu, sm, 1);
            sm += __shfl_xor_sync(0xffffffffu, sm, 2);
            sm += __shfl_xor_sync(0xffffffffu, sm, 4);
            s_att[nd][q][eh][k] = __fdividef(ex, sm + 1e-16f);
        }
    }
    __syncwarp();

    // ---- phase 4: eout ----
    #pragma unroll
    for (int rep = 0; rep < 2; rep++) {
        int u = lane + 32 * rep;
        int eh = u >> 4;
        float evr[8];
        #pragma unroll
        for (int k = 0; k < 8; k++) evr[k] = s_ev[nd][k][u];
        #pragma unroll
        for (int q = 0; q < 8; q++) {
            float4 a0 = *(const float4*)&s_att[nd][q][eh][0];
            float4 a1 = *(const float4*)&s_att[nd][q][eh][4];
            float acc = 0.f;
            acc = fmaf(a0.x, evr[0], acc); acc = fmaf(a0.y, evr[1], acc);
            acc = fmaf(a0.z, evr[2], acc); acc = fmaf(a0.w, evr[3], acc);
            acc = fmaf(a1.x, evr[4], acc); acc = fmaf(a1.y, evr[5], acc);
            acc = fmaf(a1.z, evr[6], acc); acc = fmaf(a1.w, evr[7], acc);
            s_eq[nd][q][u] = acc;
        }
    }
    __syncwarp();

    // ---- phase 5: edge_emb ----
    #pragma unroll
    for (int rep = 0; rep < 2; rep++) {
        int p = lane + 32 * rep;
        int q = p >> 3, h = p & 7;
        float acc = __ldg(&bel[h]);
        const float4* ep = (const float4*)&s_eq[nd][q][0];
        const float4* wp = (const float4*)&s_Wel[h][0];
        #pragma unroll
        for (int c = 0; c < 16; c++) {
            float4 e = ep[c], w = wp[c];
            acc += e.x * w.x + e.y * w.y + e.z * w.z + e.w * w.w;
        }
        s_ee[nd][q][h] = acc;
    }
    __syncwarp();

    // ---- phase 6a: node softmax ----
    if (lane < 8) {
        int h = lane;
        float l[8], mx = -1e30f;
        #pragma unroll
        for (int j = 0; j < 8; j++) {
            l[j] = s_ee[nd][j][h] + s_sqk[nd][j][h];
            mx = fmaxf(mx, l[j]);
        }
        float sm = 0.f;
        #pragma unroll
        for (int j = 0; j < 8; j++) { l[j] = __expf(l[j] - mx); sm += l[j]; }
        float inv = __fdividef(1.f, sm + 1e-16f);
        #pragma unroll
        for (int j = 0; j < 8; j++) s_attn[nd][j][h] = l[j] * inv;
    }
    // ---- phase 6b: edge_embeddings output ----
    #pragma unroll
    for (int rep = 0; rep < 2; rep++) {
        int p = lane + 32 * rep;
        int q = p >> 3, d2 = (p & 7) * 2;
        float a0 = __ldg(&bele[d2]), a1 = __ldg(&bele[d2 + 1]);
        #pragma unroll
        for (int h = 0; h < 8; h++) {
            float e = s_ee[nd][q][h];
            a0 = fmaf(e, s_Wele[d2][h], a0);
            a1 = fmaf(e, s_Wele[d2 + 1][h], a1);
        }
        *(float2*)&out_edge[(n * 8 + q) * 16 + d2] = make_float2(a0, a1);
    }
    __syncwarp();

    // ---- phase 7: node aggregation ----
    #pragma unroll
    for (int i = 0; i < 4; i++) {
        int c4 = lane + 32 * i;
        int h  = c4 >> 4;
        float4 acc = make_float4(0.f, 0.f, 0.f, 0.f);
        #pragma unroll
        for (int j = 0; j < 8; j++) {
            float w = s_attn[nd][j][h];
            float4 v = __ldg((const float4*)(g_nv + (long)e1r[j] * 512) + c4);
            acc.x = fmaf(w, v.x, acc.x); acc.y = fmaf(w, v.y, acc.y);
            acc.z = fmaf(w, v.z, acc.z); acc.w = fmaf(w, v.w, acc.w);
        }
        ((float4*)(g_node + (long)n * 512))[c4] = acc;
    }
}

// ---------------------------------------------------------------------------
// Kernel 3: out GEMM on the tensor pipe (tf32 mma.sync).
// out[64 rows/block, 64 d] = g_node[rows,512] @ Wlin^T + blin.
// 128 threads / 4 warps; warp owns 16 rows x 8 n-tiles; K in 8 slabs of 64.
// ---------------------------------------------------------------------------
__global__ __launch_bounds__(128) void out_gemm_kernel(
    const float* __restrict__ Wlin, const float* __restrict__ blin,
    float* __restrict__ out)
{
    __shared__ uint32_t As[64][68];   // [row][k]  tf32 bits
    __shared__ uint32_t Ws[64][68];   // [d][k]    tf32 bits

    int r0 = blockIdx.x * 64;
    int t  = threadIdx.x;
    int warp = t >> 5, lane = t & 31;
    int g  = lane >> 2;
    int tg = lane & 3;
    int mrow = warp * 16;

    float4 acc[8];
    #pragma unroll
    for (int i = 0; i < 8; i++) acc[i] = make_float4(0.f, 0.f, 0.f, 0.f);

    for (int k0g = 0; k0g < 512; k0g += 64) {
        __syncthreads();
        #pragma unroll
        for (int i = 0; i < 8; i++) {
            int idx = t + i * 128;
            int row = idx >> 4, k4 = idx & 15;
            float4 v = make_float4(0.f, 0.f, 0.f, 0.f);
            if (r0 + row < NN) v = *(const float4*)&g_node[(long)(r0 + row) * 512 + k0g + k4 * 4];
            uint4 u = make_uint4(to_tf32(v.x), to_tf32(v.y), to_tf32(v.z), to_tf32(v.w));
            *(uint4*)&As[row][k4 * 4] = u;
            float4 w = *(const float4*)&Wlin[(long)row * 512 + k0g + k4 * 4];  // row = out dim d
            uint4 uw = make_uint4(to_tf32(w.x), to_tf32(w.y), to_tf32(w.z), to_tf32(w.w));
            *(uint4*)&Ws[row][k4 * 4] = uw;
        }
        __syncthreads();

        #pragma unroll
        for (int ks = 0; ks < 8; ks++) {
            int k0 = ks * 8;
            uint32_t a0 = As[mrow + g][k0 + tg];
            uint32_t a1 = As[mrow + g + 8][k0 + tg];
            uint32_t a2 = As[mrow + g][k0 + tg + 4];
            uint32_t a3 = As[mrow + g + 8][k0 + tg + 4];
            #pragma unroll
            for (int nt = 0; nt < 8; nt++) {
                int n0 = nt * 8;
                uint32_t b0 = Ws[n0 + g][k0 + tg];
                uint32_t b1 = Ws[n0 + g][k0 + tg + 4];
                mma_tf32(acc[nt], a0, a1, a2, a3, b0, b1);
            }
        }
    }

    int row1 = r0 + mrow + g;
    int row2 = row1 + 8;
    bool ok1 = row1 < NN, ok2 = row2 < NN;
    #pragma unroll
    for (int nt = 0; nt < 8; nt++) {
        int n = nt * 8 + 2 * tg;
        float2 b2 = *(const float2*)&blin[n];
        if (ok1) *(float2*)&out[(long)row1 * 64 + n] =
            make_float2(acc[nt].x + b2.x, acc[nt].y + b2.y);
        if (ok2) *(float2*)&out[(long)row2 * 64 + n] =
            make_float2(acc[nt].z + b2.x, acc[nt].w + b2.y);
    }
}

// ---------------------------------------------------------------------------
extern "C" void kernel_launch(void* const* d_in, const int* in_sizes, int n_in,
                              void* d_out, int out_size)
{
    const float* x    = (const float*)d_in[0];
    const float* ef   = (const float*)d_in[1];
    const float* Wq   = (const float*)d_in[2];
    const float* bq   = (const float*)d_in[3];
    const float* Wk   = (const float*)d_in[4];
    const float* bk   = (const float*)d_in[5];
    const float* Wv   = (const float*)d_in[6];
    const float* bv   = (const float*)d_in[7];
    const float* Wlin = (const float*)d_in[8];
    const float* blin = (const float*)d_in[9];
    const float* Weq  = (const float*)d_in[10];
    const float* beq  = (const float*)d_in[11];
    const float* Wev  = (const float*)d_in[12];
    const float* bev  = (const float*)d_in[13];
    const float* Wek  = (const float*)d_in[14];
    const float* bek  = (const float*)d_in[15];
    const float* Wel  = (const float*)d_in[16];
    const float* bel  = (const float*)d_in[17];
    const float* Wele = (const float*)d_in[18];
    const float* bele = (const float*)d_in[19];
    const int*   eidx = (const int*)d_in[20];
    float* out = (float*)d_out;

    proj_qkv_kernel<<<dim3(12, 157), 128>>>(x, Wq, bq, Wk, bk, Wv, bv);
    node_edge_kernel<<<NN / 4, 128>>>(ef, eidx, Weq, beq, Wev, bev, Wek, bek,
                                      Wel, bel, Wele, bele, out + NN * 64);
    out_gemm_kernel<<<157, 128>>>(Wlin, blin, out);
}

// round 17
// speedup vs baseline: 1.2385x; 1.0272x over previous
#include <cuda_runtime.h>
#include <cstdint>

#define NN 10000     // nodes
#define KD 8         // out-degree
#define EE 80000     // edges
#define HDIM 512     // H*D

// Scratch (allocation-free rule: __device__ globals)
__device__ float g_nq[NN * HDIM];
__device__ float g_nk[NN * HDIM];
__device__ float g_nv[NN * HDIM];
__device__ float g_node[NN * HDIM];

// ---- helpers ----
__device__ __forceinline__ uint32_t to_tf32(float f) {
    uint32_t r;
    asm("cvt.rna.tf32.f32 %0, %1;" : "=r"(r) : "f"(f));
    return r;
}
__device__ __forceinline__ void mma_tf32(float4& d,
                                         uint32_t a0, uint32_t a1, uint32_t a2, uint32_t a3,
                                         uint32_t b0, uint32_t b1) {
    asm("mma.sync.aligned.m16n8k8.row.col.f32.tf32.tf32.f32 "
        "{%0,%1,%2,%3}, {%4,%5,%6,%7}, {%8,%9}, {%0,%1,%2,%3};"
        : "+f"(d.x), "+f"(d.y), "+f"(d.z), "+f"(d.w)
        : "r"(a0), "r"(a1), "r"(a2), "r"(a3), "r"(b0), "r"(b1));
}

// ---------------------------------------------------------------------------
// Kernel 1: fused QKV projection, tensor pipe (R16 version, 26.8us).
// ---------------------------------------------------------------------------
__global__ __launch_bounds__(128) void proj_qkv_kernel(
    const float* __restrict__ X,
    const float* __restrict__ Wq, const float* __restrict__ bq,
    const float* __restrict__ Wk, const float* __restrict__ bk,
    const float* __restrict__ Wv, const float* __restrict__ bv)
{
    __shared__ uint32_t As[64][68];    // [row][k]  tf32 bits
    __shared__ uint32_t Bs[128][68];   // [col][k]  tf32 bits

    int bx  = blockIdx.x;
    int sel = bx >> 2;
    int c0  = (bx & 3) * 128;
    int r0  = blockIdx.y * 64;
    int t   = threadIdx.x;

    const float* W    = (sel == 0) ? Wq : (sel == 1) ? Wk : Wv;
    const float* bias = (sel == 0) ? bq : (sel == 1) ? bk : bv;
    float*       outp = (sel == 0) ? g_nq : (sel == 1) ? g_nk : g_nv;

    #pragma unroll
    for (int i = 0; i < 8; i++) {
        int idx = t + i * 128;
        int row = idx >> 4, k4 = idx & 15;
        float4 v = make_float4(0.f, 0.f, 0.f, 0.f);
        if (r0 + row < NN) v = *(const float4*)&X[(r0 + row) * 64 + k4 * 4];
        uint4 u = make_uint4(to_tf32(v.x), to_tf32(v.y), to_tf32(v.z), to_tf32(v.w));
        *(uint4*)&As[row][k4 * 4] = u;
    }
    #pragma unroll
    for (int i = 0; i < 16; i++) {
        int idx = t + i * 128;
        int c = idx >> 4, k4 = idx & 15;
        float4 w = *(const float4*)&W[(c0 + c) * 64 + k4 * 4];
        uint4 u = make_uint4(to_tf32(w.x), to_tf32(w.y), to_tf32(w.z), to_tf32(w.w));
        *(uint4*)&Bs[c][k4 * 4] = u;
    }
    __syncthreads();

    int warp = t >> 5, lane = t & 31;
    int g  = lane >> 2;
    int tg = lane & 3;
    int nbase = warp * 32;

    float4 acc[4][4];
    #pragma unroll
    for (int i = 0; i < 4; i++)
        #pragma unroll
        for (int j = 0; j < 4; j++) acc[i][j] = make_float4(0.f, 0.f, 0.f, 0.f);

    #pragma unroll
    for (int ks = 0; ks < 8; ks++) {
        int k0 = ks * 8;
        uint32_t a0[4], a1[4], a2[4], a3[4];
        #pragma unroll
        for (int mt = 0; mt < 4; mt++) {
            int mr = mt * 16;
            a0[mt] = As[mr + g][k0 + tg];
            a1[mt] = As[mr + g + 8][k0 + tg];
            a2[mt] = As[mr + g][k0 + tg + 4];
            a3[mt] = As[mr + g + 8][k0 + tg + 4];
        }
        #pragma unroll
        for (int nt = 0; nt < 4; nt++) {
            int n0 = nbase + nt * 8;
            uint32_t b0 = Bs[n0 + g][k0 + tg];
            uint32_t b1 = Bs[n0 + g][k0 + tg + 4];
            #pragma unroll
            for (int mt = 0; mt < 4; mt++)
                mma_tf32(acc[mt][nt], a0[mt], a1[mt], a2[mt], a3[mt], b0, b1);
        }
    }

    #pragma unroll
    for (int mt = 0; mt < 4; mt++) {
        int row1 = r0 + mt * 16 + g;
        int row2 = row1 + 8;
        bool ok1 = row1 < NN, ok2 = row2 < NN;
        #pragma unroll
        for (int nt = 0; nt < 4; nt++) {
            int n = c0 + nbase + nt * 8 + 2 * tg;
            float2 b2 = *(const float2*)&bias[n];
            if (ok1) *(float2*)&outp[(long)row1 * HDIM + n] =
                make_float2(acc[mt][nt].x + b2.x, acc[mt][nt].y + b2.y);
            if (ok2) *(float2*)&outp[(long)row2 * HDIM + n] =
                make_float2(acc[mt][nt].z + b2.x, acc[mt][nt].w + b2.y);
        }
    }
}

// ---------------------------------------------------------------------------
// Kernel 2: warp-per-node fused pipeline; phase 2 (eq/ev/ek) on the tensor
// pipe: block's 32 edges form the M dim, warp owns a 16-col slice.
// ---------------------------------------------------------------------------
__global__ __launch_bounds__(128) void node_edge_kernel(
    const float* __restrict__ edge_features,
    const int*   __restrict__ edge_index,
    const float* __restrict__ Weq, const float* __restrict__ beq,
    const float* __restrict__ Wev, const float* __restrict__ bev,
    const float* __restrict__ Wek, const float* __restrict__ bek,
    const float* __restrict__ Wel, const float* __restrict__ bel,
    const float* __restrict__ Wele, const float* __restrict__ bele,
    float* __restrict__ out_edge)
{
    __shared__ __align__(16) float s_Wel[8][68];  // [h][c]
    __shared__ float s_Wele[16][9];               // [de][h]
    __shared__ uint32_t s_efB[32][20];            // [edge][c] tf32 bits
    __shared__ uint32_t s_sqkB[32][12];           // [edge][h] tf32 bits
    __shared__ __align__(16) float s_eq[4][8][68];   // eq, reused as eout
    __shared__ __align__(16) float s_ev[4][8][68];
    __shared__ __align__(16) float s_ek[4][8][68];
    __shared__ __align__(16) float s_att[4][8][4][8];
    __shared__ float s_sqk[4][8][8];
    __shared__ float s_ee[4][8][8];
    __shared__ float s_attn[4][8][8];

    int t    = threadIdx.x;
    int nd   = t >> 5;
    int lane = t & 31;
    int n    = blockIdx.x * 4 + nd;

    for (int i = t; i < 512; i += 128) s_Wel[i >> 6][i & 63] = Wel[i];
    s_Wele[t >> 3][t & 7] = Wele[t];

    int ej = (lane < 8) ? edge_index[EE + n * 8 + lane] : 0;
    int e1r[8];
    #pragma unroll
    for (int j = 0; j < 8; j++) e1r[j] = __shfl_sync(0xffffffffu, ej, j);

    // edge features -> tf32 staging [32 edges][16]
    {
        float4 f = ((const float4*)(edge_features + (long)n * 128))[lane];
        int er = nd * 8 + (lane >> 2);
        int c4 = (lane & 3) * 4;
        s_efB[er][c4 + 0] = to_tf32(f.x);
        s_efB[er][c4 + 1] = to_tf32(f.y);
        s_efB[er][c4 + 2] = to_tf32(f.z);
        s_efB[er][c4 + 3] = to_tf32(f.w);
    }

    // ---- phase 1: sqk head-aligned (writes fp32 + tf32 copies) ----
    {
        int hh = lane >> 2, mm = lane & 3;
        const float4* qp = (const float4*)(g_nq + (long)n * 512);
        float4 q4[4];
        #pragma unroll
        for (int i = 0; i < 4; i++) q4[i] = qp[hh * 16 + mm + 4 * i];
        #pragma unroll
        for (int j = 0; j < 8; j++) {
            const float4* kp = (const float4*)(g_nk + (long)e1r[j] * 512);
            float s = 0.f;
            #pragma unroll
            for (int i = 0; i < 4; i++) {
                float4 kv = __ldg(&kp[hh * 16 + mm + 4 * i]);
                s += q4[i].x * kv.x + q4[i].y * kv.y + q4[i].z * kv.z + q4[i].w * kv.w;
            }
            s += __shfl_xor_sync(0xffffffffu, s, 1);
            s += __shfl_xor_sync(0xffffffffu, s, 2);
            if (mm == 0) {
                float sc = s * 0.125f;
                s_sqk[nd][j][hh] = sc;
                s_sqkB[nd * 8 + j][hh] = to_tf32(sc);
            }
        }
    }
    __syncthreads();   // all warps' efB/sqkB/weights visible

    // ---- phase 2 (MMA): eq/ev/ek over the block's 32 edges ----
    {
        int g  = lane >> 2;
        int tg = lane & 3;
        int nb = nd * 16;                 // warp's 16-col slice
        float* eqf = &s_eq[0][0][0];
        float* evf = &s_ev[0][0][0];
        float* ekf = &s_ek[0][0][0];

        // -- eq and ev (K=16, 2 k-steps) --
        #pragma unroll
        for (int which = 0; which < 2; which++) {
            const float* Wp = which ? Wev : Weq;
            const float* bp = which ? bev : beq;
            float*       dst = which ? evf : eqf;
            float4 acc[2][2];
            #pragma unroll
            for (int mt = 0; mt < 2; mt++)
                #pragma unroll
                for (int nt = 0; nt < 2; nt++)
                    acc[mt][nt] = make_float4(0.f, 0.f, 0.f, 0.f);
            #pragma unroll
            for (int ks = 0; ks < 2; ks++) {
                int k0 = ks * 8;
                uint32_t a0[2], a1[2], a2[2], a3[2];
                #pragma unroll
                for (int mt = 0; mt < 2; mt++) {
                    int mr = mt * 16;
                    a0[mt] = s_efB[mr + g][k0 + tg];
                    a1[mt] = s_efB[mr + g + 8][k0 + tg];
                    a2[mt] = s_efB[mr + g][k0 + tg + 4];
                    a3[mt] = s_efB[mr + g + 8][k0 + tg + 4];
                }
                #pragma unroll
                for (int nt = 0; nt < 2; nt++) {
                    int col = nb + nt * 8 + g;
                    uint32_t b0 = to_tf32(__ldg(&Wp[col * 16 + k0 + tg]));
                    uint32_t b1 = to_tf32(__ldg(&Wp[col * 16 + k0 + tg + 4]));
                    #pragma unroll
                    for (int mt = 0; mt < 2; mt++)
                        mma_tf32(acc[mt][nt], a0[mt], a1[mt], a2[mt], a3[mt], b0, b1);
                }
            }
            #pragma unroll
            for (int mt = 0; mt < 2; mt++) {
                int r1 = mt * 16 + g;
                int r2 = r1 + 8;
                #pragma unroll
                for (int nt = 0; nt < 2; nt++) {
                    int col = nb + nt * 8 + 2 * tg;
                    float b0 = __ldg(&bp[col]), b1 = __ldg(&bp[col + 1]);
                    *(float2*)&dst[r1 * 68 + col] =
                        make_float2(acc[mt][nt].x + b0, acc[mt][nt].y + b1);
                    *(float2*)&dst[r2 * 68 + col] =
                        make_float2(acc[mt][nt].z + b0, acc[mt][nt].w + b1);
                }
            }
        }
        // -- ek (K=8, 1 k-step, A = sqk) --
        {
            float4 acc[2][2];
            #pragma unroll
            for (int mt = 0; mt < 2; mt++)
                #pragma unroll
                for (int nt = 0; nt < 2; nt++)
                    acc[mt][nt] = make_float4(0.f, 0.f, 0.f, 0.f);
            uint32_t a0[2], a1[2], a2[2], a3[2];
            #pragma unroll
            for (int mt = 0; mt < 2; mt++) {
                int mr = mt * 16;
                a0[mt] = s_sqkB[mr + g][tg];
                a1[mt] = s_sqkB[mr + g + 8][tg];
                a2[mt] = s_sqkB[mr + g][tg + 4];
                a3[mt] = s_sqkB[mr + g + 8][tg + 4];
            }
            #pragma unroll
            for (int nt = 0; nt < 2; nt++) {
                int col = nb + nt * 8 + g;
                uint32_t b0 = to_tf32(__ldg(&Wek[col * 8 + tg]));
                uint32_t b1 = to_tf32(__ldg(&Wek[col * 8 + tg + 4]));
                #pragma unroll
                for (int mt = 0; mt < 2; mt++)
                    mma_tf32(acc[mt][nt], a0[mt], a1[mt], a2[mt], a3[mt], b0, b1);
            }
            #pragma unroll
            for (int mt = 0; mt < 2; mt++) {
                int r1 = mt * 16 + g;
                int r2 = r1 + 8;
                #pragma unroll
                for (int nt = 0; nt < 2; nt++) {
                    int col = nb + nt * 8 + 2 * tg;
                    float b0 = __ldg(&bek[col]), b1 = __ldg(&bek[col + 1]);
                    *(float2*)&ekf[r1 * 68 + col] =
                        make_float2(acc[mt][nt].x + b0, acc[mt][nt].y + b1);
                    *(float2*)&ekf[r2 * 68 + col] =
                        make_float2(acc[mt][nt].z + b0, acc[mt][nt].w + b1);
                }
            }
        }
    }
    __syncthreads();   // columns of this node's rows were written by other warps

    // ---- phase 3: edge-edge attention ----
    #pragma unroll
    for (int rep = 0; rep < 2; rep++) {
        int p = lane + 32 * rep;
        int q = p >> 3, k = p & 7;
        const float4* eqp = (const float4*)&s_eq[nd][q][0];
        const float4* ekp = (const float4*)&s_ek[nd][k][0];
        #pragma unroll
        for (int eh = 0; eh < 4; eh++) {
            float s = 0.f;
            #pragma unroll
            for (int c = 0; c < 4; c++) {
                float4 a = eqp[eh * 4 + c];
                float4 b = ekp[eh * 4 + c];
                s += a.x * b.x + a.y * b.y + a.z * b.z + a.w * b.w;
            }
            s *= 0.25f;
            float mx = s;
            mx = fmaxf(mx, __shfl_xor_sync(0xffffffffu, mx, 1));
            mx = fmaxf(mx, __shfl_xor_sync(0xffffffffu, mx, 2));
            mx = fmaxf(mx, __shfl_xor_sync(0xffffffffu, mx, 4));
            float ex = __expf(s - mx);
            float sm = ex;
            sm += __shfl_xor_sync(0xffffffffu, sm, 1);
            sm += __shfl_xor_sync(0xffffffffu, sm, 2);
            sm += __shfl_xor_sync(0xffffffffu, sm, 4);
            s_att[nd][q][eh][k] = __fdividef(ex, sm + 1e-16f);
        }
    }
    __syncwarp();

    // ---- phase 4: eout ----
    #pragma unroll
    for (int rep = 0; rep < 2; rep++) {
        int u = lane + 32 * rep;
        int eh = u >> 4;
        float evr[8];
        #pragma unroll
        for (int k = 0; k < 8; k++) evr[k] = s_ev[nd][k][u];
        #pragma unroll
        for (int q = 0; q < 8; q++) {
            float4 a0 = *(const float4*)&s_att[nd][q][eh][0];
            float4 a1 = *(const float4*)&s_att[nd][q][eh][4];
            float acc = 0.f;
            acc = fmaf(a0.x, evr[0], acc); acc = fmaf(a0.y, evr[1], acc);
            acc = fmaf(a0.z, evr[2], acc); acc = fmaf(a0.w, evr[3], acc);
            acc = fmaf(a1.x, evr[4], acc); acc = fmaf(a1.y, evr[5], acc);
            acc = fmaf(a1.z, evr[6], acc); acc = fmaf(a1.w, evr[7], acc);
            s_eq[nd][q][u] = acc;          // eq reused as eout
        }
    }
    __syncwarp();

    // ---- phase 5: edge_emb ----
    #pragma unroll
    for (int rep = 0; rep < 2; rep++) {
        int p = lane + 32 * rep;
        int q = p >> 3, h = p & 7;
        float acc = __ldg(&bel[h]);
        const float4* ep = (const float4*)&s_eq[nd][q][0];
        const float4* wp = (const float4*)&s_Wel[h][0];
        #pragma unroll
        for (int c = 0; c < 16; c++) {
            float4 e = ep[c], w = wp[c];
            acc += e.x * w.x + e.y * w.y + e.z * w.z + e.w * w.w;
        }
        s_ee[nd][q][h] = acc;
    }
    __syncwarp();

    // ---- phase 6a: node softmax ----
    if (lane < 8) {
        int h = lane;
        float l[8], mx = -1e30f;
        #pragma unroll
        for (int j = 0; j < 8; j++) {
            l[j] = s_ee[nd][j][h] + s_sqk[nd][j][h];
            mx = fmaxf(mx, l[j]);
        }
        float sm = 0.f;
        #pragma unroll
        for (int j = 0; j < 8; j++) { l[j] = __expf(l[j] - mx); sm += l[j]; }
        float inv = __fdividef(1.f, sm + 1e-16f);
        #pragma unroll
        for (int j = 0; j < 8; j++) s_attn[nd][j][h] = l[j] * inv;
    }
    // ---- phase 6b: edge_embeddings output ----
    #pragma unroll
    for (int rep = 0; rep < 2; rep++) {
        int p = lane + 32 * rep;
        int q = p >> 3, d2 = (p & 7) * 2;
        float a0 = __ldg(&bele[d2]), a1 = __ldg(&bele[d2 + 1]);
        #pragma unroll
        for (int h = 0; h < 8; h++) {
            float e = s_ee[nd][q][h];
            a0 = fmaf(e, s_Wele[d2][h], a0);
            a1 = fmaf(e, s_Wele[d2 + 1][h], a1);
        }
        *(float2*)&out_edge[(n * 8 + q) * 16 + d2] = make_float2(a0, a1);
    }
    __syncwarp();

    // ---- phase 7: node aggregation ----
    #pragma unroll
    for (int i = 0; i < 4; i++) {
        int c4 = lane + 32 * i;
        int h  = c4 >> 4;
        float4 acc = make_float4(0.f, 0.f, 0.f, 0.f);
        #pragma unroll
        for (int j = 0; j < 8; j++) {
            float w = s_attn[nd][j][h];
            float4 v = __ldg((const float4*)(g_nv + (long)e1r[j] * 512) + c4);
            acc.x = fmaf(w, v.x, acc.x); acc.y = fmaf(w, v.y, acc.y);
            acc.z = fmaf(w, v.z, acc.z); acc.w = fmaf(w, v.w, acc.w);
        }
        ((float4*)(g_node + (long)n * 512))[c4] = acc;
    }
}

// ---------------------------------------------------------------------------
// Kernel 3: out GEMM on the tensor pipe (R16 version).
// ---------------------------------------------------------------------------
__global__ __launch_bounds__(128) void out_gemm_kernel(
    const float* __restrict__ Wlin, const float* __restrict__ blin,
    float* __restrict__ out)
{
    __shared__ uint32_t As[64][68];   // [row][k]  tf32 bits
    __shared__ uint32_t Ws[64][68];   // [d][k]    tf32 bits

    int r0 = blockIdx.x * 64;
    int t  = threadIdx.x;
    int warp = t >> 5, lane = t & 31;
    int g  = lane >> 2;
    int tg = lane & 3;
    int mrow = warp * 16;

    float4 acc[8];
    #pragma unroll
    for (int i = 0; i < 8; i++) acc[i] = make_float4(0.f, 0.f, 0.f, 0.f);

    for (int k0g = 0; k0g < 512; k0g += 64) {
        __syncthreads();
        #pragma unroll
        for (int i = 0; i < 8; i++) {
            int idx = t + i * 128;
            int row = idx >> 4, k4 = idx & 15;
            float4 v = make_float4(0.f, 0.f, 0.f, 0.f);
            if (r0 + row < NN) v = *(const float4*)&g_node[(long)(r0 + row) * 512 + k0g + k4 * 4];
            uint4 u = make_uint4(to_tf32(v.x), to_tf32(v.y), to_tf32(v.z), to_tf32(v.w));
            *(uint4*)&As[row][k4 * 4] = u;
            float4 w = *(const float4*)&Wlin[(long)row * 512 + k0g + k4 * 4];
            uint4 uw = make_uint4(to_tf32(w.x), to_tf32(w.y), to_tf32(w.z), to_tf32(w.w));
            *(uint4*)&Ws[row][k4 * 4] = uw;
        }
        __syncthreads();

        #pragma unroll
        for (int ks = 0; ks < 8; ks++) {
            int k0 = ks * 8;
            uint32_t a0 = As[mrow + g][k0 + tg];
            uint32_t a1 = As[mrow + g + 8][k0 + tg];
            uint32_t a2 = As[mrow + g][k0 + tg + 4];
            uint32_t a3 = As[mrow + g + 8][k0 + tg + 4];
            #pragma unroll
            for (int nt = 0; nt < 8; nt++) {
                int n0 = nt * 8;
                uint32_t b0 = Ws[n0 + g][k0 + tg];
                uint32_t b1 = Ws[n0 + g][k0 + tg + 4];
                mma_tf32(acc[nt], a0, a1, a2, a3, b0, b1);
            }
        }
    }

    int row1 = r0 + mrow + g;
    int row2 = row1 + 8;
    bool ok1 = row1 < NN, ok2 = row2 < NN;
    #pragma unroll
    for (int nt = 0; nt < 8; nt++) {
        int n = nt * 8 + 2 * tg;
        float2 b2 = *(const float2*)&blin[n];
        if (ok1) *(float2*)&out[(long)row1 * 64 + n] =
            make_float2(acc[nt].x + b2.x, acc[nt].y + b2.y);
        if (ok2) *(float2*)&out[(long)row2 * 64 + n] =
            make_float2(acc[nt].z + b2.x, acc[nt].w + b2.y);
    }
}

// ---------------------------------------------------------------------------
extern "C" void kernel_launch(void* const* d_in, const int* in_sizes, int n_in,
                              void* d_out, int out_size)
{
    const float* x    = (const float*)d_in[0];
    const float* ef   = (const float*)d_in[1];
    const float* Wq   = (const float*)d_in[2];
    const float* bq   = (const float*)d_in[3];
    const float* Wk   = (const float*)d_in[4];
    const float* bk   = (const float*)d_in[5];
    const float* Wv   = (const float*)d_in[6];
    const float* bv   = (const float*)d_in[7];
    const float* Wlin = (const float*)d_in[8];
    const float* blin = (const float*)d_in[9];
    const float* Weq  = (const float*)d_in[10];
    const float* beq  = (const float*)d_in[11];
    const float* Wev  = (const float*)d_in[12];
    const float* bev  = (const float*)d_in[13];
    const float* Wek  = (const float*)d_in[14];
    const float* bek  = (const float*)d_in[15];
    const float* Wel  = (const float*)d_in[16];
    const float* bel  = (const float*)d_in[17];
    const float* Wele = (const float*)d_in[18];
    const float* bele = (const float*)d_in[19];
    const int*   eidx = (const int*)d_in[20];
    float* out = (float*)d_out;

    proj_qkv_kernel<<<dim3(12, 157), 128>>>(x, Wq, bq, Wk, bk, Wv, bv);
    node_edge_kernel<<<NN / 4, 128>>>(ef, eidx, Weq, beq, Wev, bev, Wek, bek,
                                      Wel, bel, Wele, bele, out + NN * 64);
    out_gemm_kernel<<<157, 128>>>(Wlin, blin, out);
}